// round 4
// baseline (speedup 1.0000x reference)
#include <cuda_runtime.h>
#include <cstdint>

// Problem constants
#define N_    16
#define M_    100
#define L_    10000
#define EMB_  128
#define LTILE 128
#define NCHUNK 13          // 13*8 = 104 >= M_=100 (padded with zeros)
#define ASTRIDE 136        // attn smem row stride (floats) -> conflict-free B frags
#define CWSTRIDE 136       // cw smem row stride (floats)   -> conflict-free A frags

// Smem: attn_s[104][ASTRIDE] + cw_s[2][8][CWSTRIDE]
#define SMEM_FLOATS (104 * ASTRIDE + 2 * 8 * CWSTRIDE)

__device__ __forceinline__ uint32_t f32_to_tf32(float x) {
    uint32_t r;
    asm volatile("cvt.rna.tf32.f32 %0, %1;\n" : "=r"(r) : "f"(x));
    return r;
}

__global__ __launch_bounds__(256, 2)
void attn_fused_kernel(const float* __restrict__ self_attn,   // [N, M, EMB]
                       const float* __restrict__ self_delta,  // [N, M, L, 4]
                       const float* __restrict__ emb_table,   // [L+1, EMB]
                       const float* __restrict__ value_w,     // [M]
                       float* __restrict__ out)               // [N, L]
{
    extern __shared__ float smem[];
    float* attn_s = smem;                         // [104][ASTRIDE], tf32 bits
    float* cw_s   = smem + 104 * ASTRIDE;         // [2][8][CWSTRIDE], tf32 bits

    const int tid   = threadIdx.x;
    const int lane  = tid & 31;
    const int warp  = tid >> 5;                   // 8 warps
    const int n     = blockIdx.y;
    const int lbase = blockIdx.x * LTILE;

    // ---- Load attn[n] (100x128) into smem as tf32, pad m to 104 with zeros ----
    {
        const float* an = self_attn + (size_t)n * (M_ * EMB_);
        for (int idx = tid; idx < 104 * EMB_; idx += 256) {
            int m = idx >> 7;
            int d = idx & 127;
            float v = (m < M_) ? an[m * EMB_ + d] : 0.0f;
            attn_s[m * ASTRIDE + d] = __uint_as_float(f32_to_tf32(v));
        }
    }

    // ---- Accumulators: C = cw(128 l x 104 m) @ attn(104 m x 128 d) ----
    // Each warp owns row-tile (16 l rows), 16 d-tiles of width 8.
    float acc[16][4];
#pragma unroll
    for (int t = 0; t < 16; t++) {
        acc[t][0] = 0.f; acc[t][1] = 0.f; acc[t][2] = 0.f; acc[t][3] = 0.f;
    }

    // ---- Pipelined delta stream: chunk = 8 m values, warp w handles m=cbase+w ----
    float4 dv[4];
    const int kidx = lane & 3;                 // k (m-within-chunk) index for frags
    const int grp  = lane >> 2;                // group id 0..7
    const int aoff = warp * 16 + grp;          // local l row for A frags

    // prologue: load chunk 0
    {
        int m = warp;                          // cbase = 0
        size_t base = (size_t)(n * M_ + m) * L_ * 4;
#pragma unroll
        for (int i = 0; i < 4; i++) {
            int l = lbase + lane + 32 * i;
            dv[i] = (l < L_) ? *reinterpret_cast<const float4*>(self_delta + base + (size_t)l * 4)
                             : make_float4(0.f, 0.f, 0.f, 0.f);
        }
    }

    for (int c = 0; c < NCHUNK; c++) {
        float* cwb = cw_s + (c & 1) * (8 * CWSTRIDE);

        // reduce d, scale by w[m], convert to tf32, store to smem
        {
            int m = c * 8 + warp;
            float wm = (m < M_) ? __ldg(value_w + m) : 0.0f;
#pragma unroll
            for (int i = 0; i < 4; i++) {
                float s = (dv[i].x + dv[i].y) + (dv[i].z + dv[i].w);
                cwb[warp * CWSTRIDE + lane + 32 * i] = __uint_as_float(f32_to_tf32(s * wm));
            }
        }
        __syncthreads();   // cwb ready for all warps (also covers attn_s on c==0)

        // issue next chunk's loads (overlap with mma below)
        if (c + 1 < NCHUNK) {
            int m = (c + 1) * 8 + warp;
            bool mok = (m < M_);
            size_t base = (size_t)(n * M_ + (mok ? m : 0)) * L_ * 4;
#pragma unroll
            for (int i = 0; i < 4; i++) {
                int l = lbase + lane + 32 * i;
                dv[i] = (mok && l < L_)
                      ? *reinterpret_cast<const float4*>(self_delta + base + (size_t)l * 4)
                      : make_float4(0.f, 0.f, 0.f, 0.f);
            }
        }

        // A fragments (m16n8k8 tf32, row-major 16x8):
        //   a0:(g,      t)  a1:(g+8,    t)  a2:(g,    t+4)  a3:(g+8,  t+4)
        uint32_t a0 = __float_as_uint(cwb[kidx * CWSTRIDE + aoff]);
        uint32_t a1 = __float_as_uint(cwb[kidx * CWSTRIDE + aoff + 8]);
        uint32_t a2 = __float_as_uint(cwb[(kidx + 4) * CWSTRIDE + aoff]);
        uint32_t a3 = __float_as_uint(cwb[(kidx + 4) * CWSTRIDE + aoff + 8]);

        // B fragments: b0:(k=t, n=g), b1:(k=t+4, n=g); B[k=m][n=d] = attn[m][d]
        const float* br0 = attn_s + (c * 8 + kidx) * ASTRIDE + grp;
        const float* br1 = br0 + 4 * ASTRIDE;
#pragma unroll
        for (int dt = 0; dt < 16; dt++) {
            uint32_t b0 = __float_as_uint(br0[dt * 8]);
            uint32_t b1 = __float_as_uint(br1[dt * 8]);
            asm volatile(
                "mma.sync.aligned.m16n8k8.row.col.f32.tf32.tf32.f32 "
                "{%0,%1,%2,%3}, {%4,%5,%6,%7}, {%8,%9}, {%0,%1,%2,%3};\n"
                : "+f"(acc[dt][0]), "+f"(acc[dt][1]), "+f"(acc[dt][2]), "+f"(acc[dt][3])
                : "r"(a0), "r"(a1), "r"(a2), "r"(a3), "r"(b0), "r"(b1));
        }
        // no trailing sync needed: next STS targets the other buffer; the
        // per-iteration barrier above separates STS(buf) from mma reads 2 iters back.
    }

    // ---- Epilogue: out[n,l] = sum_d C[l][d] * emb_table[l+1][d] ----
    // C frag: c0:(g, 2t) c1:(g, 2t+1) c2:(g+8, 2t) c3:(g+8, 2t+1)
    const int r0 = lbase + warp * 16 + grp;
    const int r1 = r0 + 8;
    const int c2t = kidx * 2;
    float sum0 = 0.f, sum1 = 0.f;
#pragma unroll
    for (int dt = 0; dt < 16; dt++) {
        int col = dt * 8 + c2t;
        float2 e0 = make_float2(0.f, 0.f), e1 = make_float2(0.f, 0.f);
        if (r0 < L_) e0 = *reinterpret_cast<const float2*>(emb_table + (size_t)(r0 + 1) * EMB_ + col);
        if (r1 < L_) e1 = *reinterpret_cast<const float2*>(emb_table + (size_t)(r1 + 1) * EMB_ + col);
        sum0 += acc[dt][0] * e0.x + acc[dt][1] * e0.y;
        sum1 += acc[dt][2] * e1.x + acc[dt][3] * e1.y;
    }
    // reduce over the 4 lanes of each group (bits 0,1 of lane)
    sum0 += __shfl_xor_sync(0xffffffffu, sum0, 1);
    sum0 += __shfl_xor_sync(0xffffffffu, sum0, 2);
    sum1 += __shfl_xor_sync(0xffffffffu, sum1, 1);
    sum1 += __shfl_xor_sync(0xffffffffu, sum1, 2);

    if ((lane & 3) == 0) {
        if (r0 < L_) out[(size_t)n * L_ + r0] = sum0;
        if (r1 < L_) out[(size_t)n * L_ + r1] = sum1;
    }
}

extern "C" void kernel_launch(void* const* d_in, const int* in_sizes, int n_in,
                              void* d_out, int out_size) {
    (void)in_sizes; (void)n_in; (void)out_size;
    const float* self_attn  = (const float*)d_in[0];  // (16,100,128) f32
    const float* self_delta = (const float*)d_in[1];  // (16,100,10000,4) f32
    // d_in[2] = traj_len (unused by the reference)
    const float* emb_table  = (const float*)d_in[3];  // (10001,128) f32
    const float* value_w    = (const float*)d_in[4];  // (100,) f32
    float* out = (float*)d_out;                       // (16,10000) f32

    const int smem_bytes = SMEM_FLOATS * (int)sizeof(float);  // 65,280 B
    cudaFuncSetAttribute(attn_fused_kernel,
                         cudaFuncAttributeMaxDynamicSharedMemorySize, smem_bytes);

    dim3 grid((L_ + LTILE - 1) / LTILE, N_);   // (79, 16)
    attn_fused_kernel<<<grid, 256, smem_bytes>>>(self_attn, self_delta,
                                                 emb_table, value_w, out);
}

// round 7
// speedup vs baseline: 1.0023x; 1.0023x over previous
#include <cuda_runtime.h>
#include <cstdint>

// Problem constants
#define N_    16
#define M_    100
#define L_    10000
#define EMB_  128
#define LTILE 128
#define NCHUNK 13          // 13*8 = 104 >= M_=100 (padded with zeros)
#define ASTRIDE 136        // attn smem row stride (floats) -> conflict-free B frags
#define CWSTRIDE 136       // cw smem row stride (floats)   -> conflict-free A frags

// Smem: attn_s[104][ASTRIDE] + cw_s[2][8][CWSTRIDE]
#define SMEM_FLOATS (104 * ASTRIDE + 2 * 8 * CWSTRIDE)

__device__ __forceinline__ uint32_t f32_to_tf32(float x) {
    uint32_t r;
    asm volatile("cvt.rna.tf32.f32 %0, %1;\n" : "=r"(r) : "f"(x));
    return r;
}

__global__ __launch_bounds__(256, 2)
void attn_fused_kernel(const float* __restrict__ self_attn,   // [N, M, EMB]
                       const float* __restrict__ self_delta,  // [N, M, L, 4]
                       const float* __restrict__ emb_table,   // [L+1, EMB]
                       const float* __restrict__ value_w,     // [M]
                       float* __restrict__ out)               // [N, L]
{
    extern __shared__ float smem[];
    float* attn_s = smem;                         // [104][ASTRIDE], tf32 bits
    float* cw_s   = smem + 104 * ASTRIDE;         // [2][8][CWSTRIDE], tf32 bits

    const int tid   = threadIdx.x;
    const int lane  = tid & 31;
    const int warp  = tid >> 5;                   // 8 warps
    const int n     = blockIdx.y;
    const int lbase = blockIdx.x * LTILE;

    // ---- Load attn[n] (100x128) into smem as tf32, pad m to 104 with zeros ----
    {
        const float* an = self_attn + (size_t)n * (M_ * EMB_);
        for (int idx = tid; idx < 104 * EMB_; idx += 256) {
            int m = idx >> 7;
            int d = idx & 127;
            float v = (m < M_) ? an[m * EMB_ + d] : 0.0f;
            attn_s[m * ASTRIDE + d] = __uint_as_float(f32_to_tf32(v));
        }
    }

    // ---- Accumulators: C = cw(128 l x 104 m) @ attn(104 m x 128 d) ----
    // Each warp owns row-tile (16 l rows), 16 d-tiles of width 8.
    float acc[16][4];
#pragma unroll
    for (int t = 0; t < 16; t++) {
        acc[t][0] = 0.f; acc[t][1] = 0.f; acc[t][2] = 0.f; acc[t][3] = 0.f;
    }

    // ---- Pipelined delta stream: chunk = 8 m values, warp w handles m=cbase+w ----
    float4 dv[4];
    const int kidx = lane & 3;                 // k (m-within-chunk) index for frags
    const int grp  = lane >> 2;                // group id 0..7
    const int aoff = warp * 16 + grp;          // local l row for A frags

    // prologue: load chunk 0
    {
        int m = warp;                          // cbase = 0
        size_t base = (size_t)(n * M_ + m) * L_ * 4;
#pragma unroll
        for (int i = 0; i < 4; i++) {
            int l = lbase + lane + 32 * i;
            dv[i] = (l < L_) ? *reinterpret_cast<const float4*>(self_delta + base + (size_t)l * 4)
                             : make_float4(0.f, 0.f, 0.f, 0.f);
        }
    }

    for (int c = 0; c < NCHUNK; c++) {
        float* cwb = cw_s + (c & 1) * (8 * CWSTRIDE);

        // reduce d, scale by w[m], convert to tf32, store to smem
        {
            int m = c * 8 + warp;
            float wm = (m < M_) ? __ldg(value_w + m) : 0.0f;
#pragma unroll
            for (int i = 0; i < 4; i++) {
                float s = (dv[i].x + dv[i].y) + (dv[i].z + dv[i].w);
                cwb[warp * CWSTRIDE + lane + 32 * i] = __uint_as_float(f32_to_tf32(s * wm));
            }
        }
        __syncthreads();   // cwb ready for all warps (also covers attn_s on c==0)

        // issue next chunk's loads (overlap with mma below)
        if (c + 1 < NCHUNK) {
            int m = (c + 1) * 8 + warp;
            bool mok = (m < M_);
            size_t base = (size_t)(n * M_ + (mok ? m : 0)) * L_ * 4;
#pragma unroll
            for (int i = 0; i < 4; i++) {
                int l = lbase + lane + 32 * i;
                dv[i] = (mok && l < L_)
                      ? *reinterpret_cast<const float4*>(self_delta + base + (size_t)l * 4)
                      : make_float4(0.f, 0.f, 0.f, 0.f);
            }
        }

        // A fragments (m16n8k8 tf32, row-major 16x8):
        //   a0:(g,      t)  a1:(g+8,    t)  a2:(g,    t+4)  a3:(g+8,  t+4)
        uint32_t a0 = __float_as_uint(cwb[kidx * CWSTRIDE + aoff]);
        uint32_t a1 = __float_as_uint(cwb[kidx * CWSTRIDE + aoff + 8]);
        uint32_t a2 = __float_as_uint(cwb[(kidx + 4) * CWSTRIDE + aoff]);
        uint32_t a3 = __float_as_uint(cwb[(kidx + 4) * CWSTRIDE + aoff + 8]);

        // B fragments: b0:(k=t, n=g), b1:(k=t+4, n=g); B[k=m][n=d] = attn[m][d]
        const float* br0 = attn_s + (c * 8 + kidx) * ASTRIDE + grp;
        const float* br1 = br0 + 4 * ASTRIDE;
#pragma unroll
        for (int dt = 0; dt < 16; dt++) {
            uint32_t b0 = __float_as_uint(br0[dt * 8]);
            uint32_t b1 = __float_as_uint(br1[dt * 8]);
            asm volatile(
                "mma.sync.aligned.m16n8k8.row.col.f32.tf32.tf32.f32 "
                "{%0,%1,%2,%3}, {%4,%5,%6,%7}, {%8,%9}, {%0,%1,%2,%3};\n"
                : "+f"(acc[dt][0]), "+f"(acc[dt][1]), "+f"(acc[dt][2]), "+f"(acc[dt][3])
                : "r"(a0), "r"(a1), "r"(a2), "r"(a3), "r"(b0), "r"(b1));
        }
        // no trailing sync needed: next STS targets the other buffer; the
        // per-iteration barrier above separates STS(buf) from mma reads 2 iters back.
    }

    // ---- Epilogue: out[n,l] = sum_d C[l][d] * emb_table[l+1][d] ----
    // C frag: c0:(g, 2t) c1:(g, 2t+1) c2:(g+8, 2t) c3:(g+8, 2t+1)
    const int r0 = lbase + warp * 16 + grp;
    const int r1 = r0 + 8;
    const int c2t = kidx * 2;
    float sum0 = 0.f, sum1 = 0.f;
#pragma unroll
    for (int dt = 0; dt < 16; dt++) {
        int col = dt * 8 + c2t;
        float2 e0 = make_float2(0.f, 0.f), e1 = make_float2(0.f, 0.f);
        if (r0 < L_) e0 = *reinterpret_cast<const float2*>(emb_table + (size_t)(r0 + 1) * EMB_ + col);
        if (r1 < L_) e1 = *reinterpret_cast<const float2*>(emb_table + (size_t)(r1 + 1) * EMB_ + col);
        sum0 += acc[dt][0] * e0.x + acc[dt][1] * e0.y;
        sum1 += acc[dt][2] * e1.x + acc[dt][3] * e1.y;
    }
    // reduce over the 4 lanes of each group (bits 0,1 of lane)
    sum0 += __shfl_xor_sync(0xffffffffu, sum0, 1);
    sum0 += __shfl_xor_sync(0xffffffffu, sum0, 2);
    sum1 += __shfl_xor_sync(0xffffffffu, sum1, 1);
    sum1 += __shfl_xor_sync(0xffffffffu, sum1, 2);

    if ((lane & 3) == 0) {
        if (r0 < L_) out[(size_t)n * L_ + r0] = sum0;
        if (r1 < L_) out[(size_t)n * L_ + r1] = sum1;
    }
}

extern "C" void kernel_launch(void* const* d_in, const int* in_sizes, int n_in,
                              void* d_out, int out_size) {
    (void)in_sizes; (void)n_in; (void)out_size;
    const float* self_attn  = (const float*)d_in[0];  // (16,100,128) f32
    const float* self_delta = (const float*)d_in[1];  // (16,100,10000,4) f32
    // d_in[2] = traj_len (unused by the reference)
    const float* emb_table  = (const float*)d_in[3];  // (10001,128) f32
    const float* value_w    = (const float*)d_in[4];  // (100,) f32
    float* out = (float*)d_out;                       // (16,10000) f32

    const int smem_bytes = SMEM_FLOATS * (int)sizeof(float);  // 65,280 B
    cudaFuncSetAttribute(attn_fused_kernel,
                         cudaFuncAttributeMaxDynamicSharedMemorySize, smem_bytes);

    dim3 grid((L_ + LTILE - 1) / LTILE, N_);   // (79, 16)
    attn_fused_kernel<<<grid, 256, smem_bytes>>>(self_attn, self_delta,
                                                 emb_table, value_w, out);
}